// round 2
// baseline (speedup 1.0000x reference)
#include <cuda_runtime.h>
#include <math.h>

#define BB 4
#define HH 256
#define WW 512
#define CC 64
#define DD 128
#define HW (HH*WW)

// Scratch feature maps (NCHW), 128 MB each. Device globals: allowed (no cudaMalloc).
__device__ float g_bufA[BB*CC*HW];
__device__ float g_bufB[BB*CC*HW];
__device__ float g_phiL[BB*CC*HW];
__device__ float g_phiR[BB*CC*HW];

// Packed dual-fp32 FMA (Blackwell): d = a*b + d lanewise on {lo,hi} f32 pairs.
__device__ __forceinline__ void ffma2(unsigned long long& d,
                                      const unsigned long long a,
                                      const unsigned long long b) {
    asm("fma.rn.f32x2 %0, %1, %2, %0;" : "+l"(d) : "l"(a), "l"(b));
}

// ---------------------------------------------------------------------------
// 3x3 SAME conv, NCHW, CIN -> 64 channels, optional ReLU.
// Block: 256 threads = 256 consecutive x at one (b, y) row; each thread owns
// all 64 output channels (as 32 packed f32x2 accumulators).
// Weights staged in smem as ws[(i*9+tap)*64 + o] (o contiguous -> warp-uniform
// broadcast reads as ulonglong2 / LDS.128).
// ---------------------------------------------------------------------------
template<int CIN, bool RELU>
__global__ void __launch_bounds__(256, 1) conv3x3_kernel(
    const float* __restrict__ in,   // [B, CIN, H, W]
    const float* __restrict__ wg,   // [64, CIN, 3, 3]
    const float* __restrict__ bg,   // [64]
    float* __restrict__ out)        // [B, 64, H, W]
{
    extern __shared__ float ws[];   // CIN*9*64 floats
    __shared__ float bs[64];

    const int tid = threadIdx.x;
    const int x   = blockIdx.x * 256 + tid;
    const int y   = blockIdx.y;
    const int b   = blockIdx.z;

    // Stage weights, transposed to [i*9+tap][o]
    for (int idx = tid; idx < CIN*9*64; idx += 256) {
        const int o  = idx & 63;
        const int it = idx >> 6;          // i*9 + tap
        const int i  = it / 9;
        const int tap = it - i*9;
        ws[idx] = wg[(o*CIN + i)*9 + tap];
    }
    if (tid < 64) bs[tid] = bg[tid];
    __syncthreads();

    unsigned long long acc[32];
    {
        const unsigned long long* bs2 = reinterpret_cast<const unsigned long long*>(bs);
        #pragma unroll
        for (int q = 0; q < 32; q++) acc[q] = bs2[q];
    }

    const float* inb = in + (size_t)b * CIN * HW;

    #pragma unroll
    for (int dy = -1; dy <= 1; dy++) {
        const int yy = y + dy;
        if (yy < 0 || yy >= HH) continue;
        #pragma unroll
        for (int dx = -1; dx <= 1; dx++) {
            const int xx  = x + dx;
            const bool ok = (xx >= 0) && (xx < WW);
            const int tap = (dy+1)*3 + (dx+1);
            const float* ip = inb + (size_t)yy * WW + xx;
            #pragma unroll 4
            for (int i = 0; i < CIN; i++) {
                const float v = ok ? __ldg(ip + (size_t)i * HW) : 0.0f;
                unsigned long long v2;
                asm("mov.b64 %0, {%1, %1};" : "=l"(v2) : "f"(v));
                const ulonglong2* wv =
                    reinterpret_cast<const ulonglong2*>(ws + (i*9 + tap)*64);
                #pragma unroll
                for (int q = 0; q < 16; q++) {
                    const ulonglong2 wq = wv[q];
                    ffma2(acc[2*q],     v2, wq.x);
                    ffma2(acc[2*q + 1], v2, wq.y);
                }
            }
        }
    }

    float* ob = out + (size_t)b * 64 * HW + (size_t)y * WW + x;
    #pragma unroll
    for (int q = 0; q < 32; q++) {
        float2 f = *reinterpret_cast<float2*>(&acc[q]);
        float v0 = RELU ? fmaxf(f.x, 0.0f) : f.x;
        float v1 = RELU ? fmaxf(f.y, 0.0f) : f.y;
        ob[(size_t)(2*q)     * HW] = v0;
        ob[(size_t)(2*q + 1) * HW] = v1;
    }
}

// ---------------------------------------------------------------------------
// Fused correlation (D=128 disparities, dot over 64 channels) + softmax over d.
// Block: 256 threads covering 64 x-positions x 128 disparities at one (b,y).
// smem: sL [c][64] (16KB), sR [c][192] covering x0-128..x0+63 (48KB),
//       rm/rs [16][64] softmax partials (8KB). Total 72KB dynamic.
// Thread tile: 4 px x 8 d  (32 FMA per 4 aligned LDS.128 per channel).
// ---------------------------------------------------------------------------
__global__ void __launch_bounds__(256, 1) corr_softmax_kernel(
    const float* __restrict__ L,    // [B, 64, H, W]
    const float* __restrict__ R,    // [B, 64, H, W]
    float* __restrict__ out)        // [B, 128, H, W]
{
    extern __shared__ float sm[];
    float* sL = sm;                  // 64*64
    float* sR = sm + 64*64;          // 64*192
    float* rm = sR + 64*192;         // 16*64
    float* rs = rm + 16*64;          // 16*64

    const int tid = threadIdx.x;
    const int x0  = blockIdx.x * 64;
    const int y   = blockIdx.y;
    const int b   = blockIdx.z;

    const float* Lb = L + (size_t)b * 64 * HW + (size_t)y * WW;
    const float* Rb = R + (size_t)b * 64 * HW + (size_t)y * WW;

    for (int idx = tid; idx < 64*64; idx += 256) {
        const int c = idx >> 6, xi = idx & 63;
        sL[c*64 + xi] = Lb[(size_t)c * HW + x0 + xi];
    }
    for (int idx = tid; idx < 64*192; idx += 256) {
        const int c = idx / 192, u = idx - c*192;
        const int gx = x0 - 128 + u;
        sR[c*192 + u] = (gx >= 0) ? Rb[(size_t)c * HW + gx] : 0.0f;
    }
    __syncthreads();

    const int xg = tid & 15;           // x-group (4 px each)
    const int dg = tid >> 4;           // d-group (8 d each)
    const int xb = xg * 4;
    const int db = dg * 8;
    const int rb = 120 + xb - db;      // 4-aligned base into sR row

    float acc[4][8];
    #pragma unroll
    for (int j = 0; j < 4; j++)
        #pragma unroll
        for (int k = 0; k < 8; k++) acc[j][k] = 0.0f;

    for (int c = 0; c < 64; c++) {
        const float4 lv = *reinterpret_cast<const float4*>(sL + c*64 + xb);
        const float4 r0 = *reinterpret_cast<const float4*>(sR + c*192 + rb);
        const float4 r1 = *reinterpret_cast<const float4*>(sR + c*192 + rb + 4);
        const float4 r2 = *reinterpret_cast<const float4*>(sR + c*192 + rb + 8);
        const float lf[4] = {lv.x, lv.y, lv.z, lv.w};
        const float rr[12] = {r0.x, r0.y, r0.z, r0.w,
                              r1.x, r1.y, r1.z, r1.w,
                              r2.x, r2.y, r2.z, r2.w};
        // R index: u = rb + 8 + j - k  ->  rr[8 + j - k]
        #pragma unroll
        for (int j = 0; j < 4; j++)
            #pragma unroll
            for (int k = 0; k < 8; k++)
                acc[j][k] = fmaf(lf[j], rr[8 + j - k], acc[j][k]);
    }

    // ---- softmax over d (cross-thread over the 16 d-groups) ----
    float lmax[4];
    #pragma unroll
    for (int j = 0; j < 4; j++) {
        float m = acc[j][0];
        #pragma unroll
        for (int k = 1; k < 8; k++) m = fmaxf(m, acc[j][k]);
        lmax[j] = m;
        rm[dg*64 + xb + j] = m;
    }
    __syncthreads();

    float m[4];
    #pragma unroll
    for (int j = 0; j < 4; j++) {
        float mm = rm[xb + j];
        #pragma unroll
        for (int g = 1; g < 16; g++) mm = fmaxf(mm, rm[g*64 + xb + j]);
        m[j] = mm;
    }

    float lsum[4] = {0.0f, 0.0f, 0.0f, 0.0f};
    #pragma unroll
    for (int j = 0; j < 4; j++) {
        #pragma unroll
        for (int k = 0; k < 8; k++) {
            const float e = __expf(acc[j][k] - m[j]);
            acc[j][k] = e;
            lsum[j] += e;
        }
        rs[dg*64 + xb + j] = lsum[j];
    }
    __syncthreads();

    float inv[4];
    #pragma unroll
    for (int j = 0; j < 4; j++) {
        float s = 0.0f;
        #pragma unroll
        for (int g = 0; g < 16; g++) s += rs[g*64 + xb + j];
        inv[j] = 1.0f / s;
    }

    #pragma unroll
    for (int k = 0; k < 8; k++) {
        const float4 o4 = make_float4(acc[0][k]*inv[0], acc[1][k]*inv[1],
                                      acc[2][k]*inv[2], acc[3][k]*inv[3]);
        float* op = out + ((size_t)(b*DD + db + k) * HH + y) * WW + x0 + xb;
        *reinterpret_cast<float4*>(op) = o4;
    }
}

// ---------------------------------------------------------------------------
extern "C" void kernel_launch(void* const* d_in, const int* in_sizes, int n_in,
                              void* d_out, int out_size)
{
    (void)in_sizes; (void)n_in; (void)out_size;
    const float* l   = (const float*)d_in[0];
    const float* r   = (const float*)d_in[1];
    const float* lw0 = (const float*)d_in[2];
    const float* lb0 = (const float*)d_in[3];
    const float* lw  = (const float*)d_in[4];   // [4,64,64,3,3]
    const float* lb  = (const float*)d_in[5];   // [4,64]
    const float* rw0 = (const float*)d_in[6];
    const float* rb0 = (const float*)d_in[7];
    const float* rw  = (const float*)d_in[8];
    const float* rb  = (const float*)d_in[9];
    float* out = (float*)d_out;

    float *bufA, *bufB, *phiL, *phiR;
    cudaGetSymbolAddress((void**)&bufA, g_bufA);
    cudaGetSymbolAddress((void**)&bufB, g_bufB);
    cudaGetSymbolAddress((void**)&phiL, g_phiL);
    cudaGetSymbolAddress((void**)&phiR, g_phiR);

    const int SM0 = 3  * 9 * 64 * 4;                       //   6912 B
    const int SM1 = 64 * 9 * 64 * 4;                       // 147456 B
    const int SMC = (64*64 + 64*192 + 2*16*64) * 4;        //  73728 B

    cudaFuncSetAttribute(conv3x3_kernel<3,  true>,
                         cudaFuncAttributeMaxDynamicSharedMemorySize, SM0);
    cudaFuncSetAttribute(conv3x3_kernel<64, true>,
                         cudaFuncAttributeMaxDynamicSharedMemorySize, SM1);
    cudaFuncSetAttribute(conv3x3_kernel<64, false>,
                         cudaFuncAttributeMaxDynamicSharedMemorySize, SM1);
    cudaFuncSetAttribute(corr_softmax_kernel,
                         cudaFuncAttributeMaxDynamicSharedMemorySize, SMC);

    const dim3 cgrid(WW/256, HH, BB);
    const size_t WL = (size_t)64*64*9;   // weights per mid layer

    // Left tower: conv0(ReLU) -> 3x conv(ReLU) -> conv(linear) => phiL
    conv3x3_kernel<3,  true ><<<cgrid, 256, SM0>>>(l,    lw0,        lb0,      bufA);
    conv3x3_kernel<64, true ><<<cgrid, 256, SM1>>>(bufA, lw + 0*WL,  lb + 0,   bufB);
    conv3x3_kernel<64, true ><<<cgrid, 256, SM1>>>(bufB, lw + 1*WL,  lb + 64,  bufA);
    conv3x3_kernel<64, true ><<<cgrid, 256, SM1>>>(bufA, lw + 2*WL,  lb + 128, bufB);
    conv3x3_kernel<64, false><<<cgrid, 256, SM1>>>(bufB, lw + 3*WL,  lb + 192, phiL);

    // Right tower => phiR
    conv3x3_kernel<3,  true ><<<cgrid, 256, SM0>>>(r,    rw0,        rb0,      bufA);
    conv3x3_kernel<64, true ><<<cgrid, 256, SM1>>>(bufA, rw + 0*WL,  rb + 0,   bufB);
    conv3x3_kernel<64, true ><<<cgrid, 256, SM1>>>(bufB, rw + 1*WL,  rb + 64,  bufA);
    conv3x3_kernel<64, true ><<<cgrid, 256, SM1>>>(bufA, rw + 2*WL,  rb + 128, bufB);
    conv3x3_kernel<64, false><<<cgrid, 256, SM1>>>(bufB, rw + 3*WL,  rb + 192, phiR);

    // Fused correlation + softmax
    const dim3 ggrid(WW/64, HH, BB);
    corr_softmax_kernel<<<ggrid, 256, SMC>>>(phiL, phiR, out);
}

// round 3
// speedup vs baseline: 1.0011x; 1.0011x over previous
#include <cuda_runtime.h>
#include <math.h>

#define BB 4
#define HH 256
#define WW 512
#define CC 64
#define DD 128
#define HW (HH*WW)

// Scratch feature maps (NCHW), 128 MB each. Device globals: allowed (no cudaMalloc).
__device__ float g_bufA[BB*CC*HW];
__device__ float g_bufB[BB*CC*HW];
__device__ float g_phiL[BB*CC*HW];
__device__ float g_phiR[BB*CC*HW];

// Packed dual-fp32 FMA (Blackwell): d = a*b + d lanewise on {lo,hi} f32 pairs.
__device__ __forceinline__ void ffma2(unsigned long long& d,
                                      const unsigned long long a,
                                      const unsigned long long b) {
    asm("fma.rn.f32x2 %0, %1, %2, %0;" : "+l"(d) : "l"(a), "l"(b));
}

// ---------------------------------------------------------------------------
// 3x3 SAME conv, NCHW, CIN -> 64 channels, optional ReLU.
// Block: 256 threads = 256 consecutive x at one (b, y) row; each thread owns
// all 64 output channels (as 32 packed f32x2 accumulators).
// Weights staged in smem as ws[(i*9+tap)*64 + o] (o contiguous -> warp-uniform
// broadcast reads as ulonglong2 / LDS.128).
// ---------------------------------------------------------------------------
template<int CIN, bool RELU>
__global__ void __launch_bounds__(256, 1) conv3x3_kernel(
    const float* __restrict__ in,   // [B, CIN, H, W]
    const float* __restrict__ wg,   // [64, CIN, 3, 3]
    const float* __restrict__ bg,   // [64]
    float* __restrict__ out)        // [B, 64, H, W]
{
    extern __shared__ float ws[];   // CIN*9*64 floats
    __shared__ float bs[64];

    const int tid = threadIdx.x;
    const int x   = blockIdx.x * 256 + tid;
    const int y   = blockIdx.y;
    const int b   = blockIdx.z;

    // Stage weights, transposed to [i*9+tap][o]
    for (int idx = tid; idx < CIN*9*64; idx += 256) {
        const int o  = idx & 63;
        const int it = idx >> 6;          // i*9 + tap
        const int i  = it / 9;
        const int tap = it - i*9;
        ws[idx] = wg[(o*CIN + i)*9 + tap];
    }
    if (tid < 64) bs[tid] = bg[tid];
    __syncthreads();

    unsigned long long acc[32];
    {
        const unsigned long long* bs2 = reinterpret_cast<const unsigned long long*>(bs);
        #pragma unroll
        for (int q = 0; q < 32; q++) acc[q] = bs2[q];
    }

    const float* inb = in + (size_t)b * CIN * HW;

    #pragma unroll
    for (int dy = -1; dy <= 1; dy++) {
        const int yy = y + dy;
        if (yy < 0 || yy >= HH) continue;
        #pragma unroll
        for (int dx = -1; dx <= 1; dx++) {
            const int xx  = x + dx;
            const bool ok = (xx >= 0) && (xx < WW);
            const int tap = (dy+1)*3 + (dx+1);
            const float* ip = inb + (size_t)yy * WW + xx;
            #pragma unroll 4
            for (int i = 0; i < CIN; i++) {
                const float v = ok ? __ldg(ip + (size_t)i * HW) : 0.0f;
                unsigned long long v2;
                asm("mov.b64 %0, {%1, %1};" : "=l"(v2) : "f"(v));
                const ulonglong2* wv =
                    reinterpret_cast<const ulonglong2*>(ws + (i*9 + tap)*64);
                #pragma unroll
                for (int q = 0; q < 16; q++) {
                    const ulonglong2 wq = wv[q];
                    ffma2(acc[2*q],     v2, wq.x);
                    ffma2(acc[2*q + 1], v2, wq.y);
                }
            }
        }
    }

    float* ob = out + (size_t)b * 64 * HW + (size_t)y * WW + x;
    #pragma unroll
    for (int q = 0; q < 32; q++) {
        float2 f = *reinterpret_cast<float2*>(&acc[q]);
        float v0 = RELU ? fmaxf(f.x, 0.0f) : f.x;
        float v1 = RELU ? fmaxf(f.y, 0.0f) : f.y;
        ob[(size_t)(2*q)     * HW] = v0;
        ob[(size_t)(2*q + 1) * HW] = v1;
    }
}

// ---------------------------------------------------------------------------
// Fused correlation (D=128 disparities, dot over 64 channels) + softmax over d.
// Block: 256 threads covering 64 x-positions x 128 disparities at one (b,y).
// smem: sL [c][64] (16KB), sR [c][192] covering x0-128..x0+63 (48KB),
//       rm/rs [16][64] softmax partials (8KB). Total 72KB dynamic.
// Thread tile: 4 px x 8 d  (32 FMA per 4 aligned LDS.128 per channel).
// ---------------------------------------------------------------------------
__global__ void __launch_bounds__(256, 1) corr_softmax_kernel(
    const float* __restrict__ L,    // [B, 64, H, W]
    const float* __restrict__ R,    // [B, 64, H, W]
    float* __restrict__ out)        // [B, 128, H, W]
{
    extern __shared__ float sm[];
    float* sL = sm;                  // 64*64
    float* sR = sm + 64*64;          // 64*192
    float* rm = sR + 64*192;         // 16*64
    float* rs = rm + 16*64;          // 16*64

    const int tid = threadIdx.x;
    const int x0  = blockIdx.x * 64;
    const int y   = blockIdx.y;
    const int b   = blockIdx.z;

    const float* Lb = L + (size_t)b * 64 * HW + (size_t)y * WW;
    const float* Rb = R + (size_t)b * 64 * HW + (size_t)y * WW;

    for (int idx = tid; idx < 64*64; idx += 256) {
        const int c = idx >> 6, xi = idx & 63;
        sL[c*64 + xi] = Lb[(size_t)c * HW + x0 + xi];
    }
    for (int idx = tid; idx < 64*192; idx += 256) {
        const int c = idx / 192, u = idx - c*192;
        const int gx = x0 - 128 + u;
        sR[c*192 + u] = (gx >= 0) ? Rb[(size_t)c * HW + gx] : 0.0f;
    }
    __syncthreads();

    const int xg = tid & 15;           // x-group (4 px each)
    const int dg = tid >> 4;           // d-group (8 d each)
    const int xb = xg * 4;
    const int db = dg * 8;
    const int rb = 120 + xb - db;      // 4-aligned base into sR row

    float acc[4][8];
    #pragma unroll
    for (int j = 0; j < 4; j++)
        #pragma unroll
        for (int k = 0; k < 8; k++) acc[j][k] = 0.0f;

    for (int c = 0; c < 64; c++) {
        const float4 lv = *reinterpret_cast<const float4*>(sL + c*64 + xb);
        const float4 r0 = *reinterpret_cast<const float4*>(sR + c*192 + rb);
        const float4 r1 = *reinterpret_cast<const float4*>(sR + c*192 + rb + 4);
        const float4 r2 = *reinterpret_cast<const float4*>(sR + c*192 + rb + 8);
        const float lf[4] = {lv.x, lv.y, lv.z, lv.w};
        const float rr[12] = {r0.x, r0.y, r0.z, r0.w,
                              r1.x, r1.y, r1.z, r1.w,
                              r2.x, r2.y, r2.z, r2.w};
        // R index: u = rb + 8 + j - k  ->  rr[8 + j - k]
        #pragma unroll
        for (int j = 0; j < 4; j++)
            #pragma unroll
            for (int k = 0; k < 8; k++)
                acc[j][k] = fmaf(lf[j], rr[8 + j - k], acc[j][k]);
    }

    // ---- softmax over d (cross-thread over the 16 d-groups) ----
    float lmax[4];
    #pragma unroll
    for (int j = 0; j < 4; j++) {
        float m = acc[j][0];
        #pragma unroll
        for (int k = 1; k < 8; k++) m = fmaxf(m, acc[j][k]);
        lmax[j] = m;
        rm[dg*64 + xb + j] = m;
    }
    __syncthreads();

    float m[4];
    #pragma unroll
    for (int j = 0; j < 4; j++) {
        float mm = rm[xb + j];
        #pragma unroll
        for (int g = 1; g < 16; g++) mm = fmaxf(mm, rm[g*64 + xb + j]);
        m[j] = mm;
    }

    float lsum[4] = {0.0f, 0.0f, 0.0f, 0.0f};
    #pragma unroll
    for (int j = 0; j < 4; j++) {
        #pragma unroll
        for (int k = 0; k < 8; k++) {
            const float e = __expf(acc[j][k] - m[j]);
            acc[j][k] = e;
            lsum[j] += e;
        }
        rs[dg*64 + xb + j] = lsum[j];
    }
    __syncthreads();

    float inv[4];
    #pragma unroll
    for (int j = 0; j < 4; j++) {
        float s = 0.0f;
        #pragma unroll
        for (int g = 0; g < 16; g++) s += rs[g*64 + xb + j];
        inv[j] = 1.0f / s;
    }

    #pragma unroll
    for (int k = 0; k < 8; k++) {
        const float4 o4 = make_float4(acc[0][k]*inv[0], acc[1][k]*inv[1],
                                      acc[2][k]*inv[2], acc[3][k]*inv[3]);
        float* op = out + ((size_t)(b*DD + db + k) * HH + y) * WW + x0 + xb;
        *reinterpret_cast<float4*>(op) = o4;
    }
}

// ---------------------------------------------------------------------------
extern "C" void kernel_launch(void* const* d_in, const int* in_sizes, int n_in,
                              void* d_out, int out_size)
{
    (void)in_sizes; (void)n_in; (void)out_size;
    const float* l   = (const float*)d_in[0];
    const float* r   = (const float*)d_in[1];
    const float* lw0 = (const float*)d_in[2];
    const float* lb0 = (const float*)d_in[3];
    const float* lw  = (const float*)d_in[4];   // [4,64,64,3,3]
    const float* lb  = (const float*)d_in[5];   // [4,64]
    const float* rw0 = (const float*)d_in[6];
    const float* rb0 = (const float*)d_in[7];
    const float* rw  = (const float*)d_in[8];
    const float* rb  = (const float*)d_in[9];
    float* out = (float*)d_out;

    float *bufA, *bufB, *phiL, *phiR;
    cudaGetSymbolAddress((void**)&bufA, g_bufA);
    cudaGetSymbolAddress((void**)&bufB, g_bufB);
    cudaGetSymbolAddress((void**)&phiL, g_phiL);
    cudaGetSymbolAddress((void**)&phiR, g_phiR);

    const int SM0 = 3  * 9 * 64 * 4;                       //   6912 B
    const int SM1 = 64 * 9 * 64 * 4;                       // 147456 B
    const int SMC = (64*64 + 64*192 + 2*16*64) * 4;        //  73728 B

    cudaFuncSetAttribute(conv3x3_kernel<3,  true>,
                         cudaFuncAttributeMaxDynamicSharedMemorySize, SM0);
    cudaFuncSetAttribute(conv3x3_kernel<64, true>,
                         cudaFuncAttributeMaxDynamicSharedMemorySize, SM1);
    cudaFuncSetAttribute(conv3x3_kernel<64, false>,
                         cudaFuncAttributeMaxDynamicSharedMemorySize, SM1);
    cudaFuncSetAttribute(corr_softmax_kernel,
                         cudaFuncAttributeMaxDynamicSharedMemorySize, SMC);

    const dim3 cgrid(WW/256, HH, BB);
    const size_t WL = (size_t)64*64*9;   // weights per mid layer

    // Left tower: conv0(ReLU) -> 3x conv(ReLU) -> conv(linear) => phiL
    conv3x3_kernel<3,  true ><<<cgrid, 256, SM0>>>(l,    lw0,        lb0,      bufA);
    conv3x3_kernel<64, true ><<<cgrid, 256, SM1>>>(bufA, lw + 0*WL,  lb + 0,   bufB);
    conv3x3_kernel<64, true ><<<cgrid, 256, SM1>>>(bufB, lw + 1*WL,  lb + 64,  bufA);
    conv3x3_kernel<64, true ><<<cgrid, 256, SM1>>>(bufA, lw + 2*WL,  lb + 128, bufB);
    conv3x3_kernel<64, false><<<cgrid, 256, SM1>>>(bufB, lw + 3*WL,  lb + 192, phiL);

    // Right tower => phiR
    conv3x3_kernel<3,  true ><<<cgrid, 256, SM0>>>(r,    rw0,        rb0,      bufA);
    conv3x3_kernel<64, true ><<<cgrid, 256, SM1>>>(bufA, rw + 0*WL,  rb + 0,   bufB);
    conv3x3_kernel<64, true ><<<cgrid, 256, SM1>>>(bufB, rw + 1*WL,  rb + 64,  bufA);
    conv3x3_kernel<64, true ><<<cgrid, 256, SM1>>>(bufA, rw + 2*WL,  rb + 128, bufB);
    conv3x3_kernel<64, false><<<cgrid, 256, SM1>>>(bufB, rw + 3*WL,  rb + 192, phiR);

    // Fused correlation + softmax
    const dim3 ggrid(WW/64, HH, BB);
    corr_softmax_kernel<<<ggrid, 256, SMC>>>(phiL, phiR, out);
}